// round 12
// baseline (speedup 1.0000x reference)
#include <cuda_runtime.h>
#include <cuda_fp16.h>

// Problem constants (fixed by setup_inputs)
#define BB 8
#define MM 4096
#define KK 2048
#define NITER 32
#define FI (5.0f/6.0f)     // reg_m / (reg_m + reg) = 0.5/0.6
#define REG 0.1f

// fused-kernel geometry: 256 thr (8 warps), 64 rows per block (8 batches
// of 8), warp owns a 256-column strip, lane owns 8 contiguous columns.
// Grid = 512 blocks -> ~3 resident blocks/SM with the (256,3) bound.
#define ROWS_PER_BLK 64
#define NBATCH       (ROWS_PER_BLK/8)       // 8
#define BLKS_PER_B   (MM/ROWS_PER_BLK)      // 64 blocks per batch
#define NPART        BLKS_PER_B             // 64 column partials per batch

// ---------------- scratch (device globals; no runtime allocation) ----------
__device__ unsigned char g_K8[(size_t)BB*MM*KK];   // e4m3 K, [b][m][k]
__device__ float  g_ctp[(size_t)BB*NPART*KK];      // per-block column partials
__device__ float  g_u [BB*MM];
__device__ float  g_v [BB*KK];
__device__ float  g_max[BB];
__device__ float  g_acc[3];                        // ssq, sum_survival, sum_bce

// ---------------- fp8 helpers ------------------------------------------------
__device__ __forceinline__ float2 fp8x2_to_float2(unsigned short s) {
    unsigned int h;
    asm("cvt.rn.f16x2.e4m3x2 %0, %1;" : "=r"(h) : "h"(s));
    return __half22float2(*(__half2*)&h);
}
__device__ __forceinline__ __half2 fp8x2_to_half2(unsigned int s) {
    unsigned int h;
    asm("cvt.rn.f16x2.e4m3x2 %0, %1;" : "=r"(h) : "h"((unsigned short)s));
    return *(__half2*)&h;
}
__device__ __forceinline__ unsigned short float2_to_fp8x2(float lo, float hi) {
    unsigned short s;
    asm("cvt.rn.satfinite.e4m3x2.f32 %0, %1, %2;" : "=h"(s) : "f"(hi), "f"(lo));
    return s;  // first source -> high byte, second -> low byte
}

// ---------------- fast exp(-x) on the FMA pipe (x >= 0, x <= ~15) -----------
__device__ __forceinline__ float fast_exp_neg(float x) {
    float t  = -x * 1.4426950408889634f;          // log2(e)
    float fl = floorf(t);
    float f  = t - fl;                            // [0,1)
    float g  = f * 0.6931471805599453f;           // ln2 * f
    float p = 1.0f + g*(1.0f + g*(0.5f + g*(0.16666667f +
              g*(0.041666667f + g*(0.0083333333f + g*0.0013888889f)))));
    int i = (int)fl;
    return p * __int_as_float((i + 127) << 23);
}

// ---------------- init ------------------------------------------------------
__global__ void k_init() {
    int i = blockIdx.x * blockDim.x + threadIdx.x;
    if (i < BB * KK) g_v[i] = 1.0f / (float)KK;
    if (i < BB)      g_max[i] = 0.0f;
    if (i < 3)       g_acc[i] = 0.0f;
}

// ---------------- per-batch max of cost matrix ------------------------------
__global__ void __launch_bounds__(256) k_max(const float* __restrict__ x0,
                                             const float* __restrict__ xgt) {
    __shared__ float4 st[KK];
    __shared__ float  wm[8];
    int b    = blockIdx.x / (MM / 8);
    int row0 = (blockIdx.x % (MM / 8)) * 8;
    const float* tg = xgt + (size_t)b * KK * 3;
    for (int j = threadIdx.x; j < KK; j += 256) {
        float tx = tg[j*3], ty = tg[j*3+1], tz = tg[j*3+2];
        st[j] = make_float4(tx, ty, tz, tx*tx + ty*ty + tz*tz);
    }
    __syncthreads();
    int w = threadIdx.x >> 5, lane = threadIdx.x & 31;
    int row = row0 + w;
    const float* s = x0 + ((size_t)b * MM + row) * 3;
    float sx = s[0], sy = s[1], sz = s[2];
    float s2 = sx*sx + sy*sy + sz*sz;
    float mx = 0.0f;
    for (int j = lane; j < KK; j += 32) {
        float4 t = st[j];
        float c = s2 + t.w - 2.0f * (sx*t.x + sy*t.y + sz*t.z);
        mx = fmaxf(mx, c);
    }
    #pragma unroll
    for (int o = 16; o; o >>= 1) mx = fmaxf(mx, __shfl_xor_sync(~0u, mx, o));
    if (lane == 0) wm[w] = mx;
    __syncthreads();
    if (threadIdx.x == 0) {
        float m = wm[0];
        #pragma unroll
        for (int i = 1; i < 8; i++) m = fmaxf(m, wm[i]);
        atomicMax((int*)&g_max[b], __float_as_int(m));  // nonneg floats: int order ok
    }
}

// ---------------- build K (e4m3), FMA-pipe exp ------------------------------
__global__ void __launch_bounds__(256) k_build(const float* __restrict__ x0,
                                               const float* __restrict__ xgt) {
    __shared__ float4 ss[64], st[64];
    int b  = blockIdx.z;
    int r0 = blockIdx.y * 64, c0 = blockIdx.x * 64;
    if (threadIdx.x < 64) {
        int r = r0 + threadIdx.x;
        const float* s = x0 + ((size_t)b * MM + r) * 3;
        float x = s[0], y = s[1], z = s[2];
        ss[threadIdx.x] = make_float4(x, y, z, x*x + y*y + z*z);
    } else if (threadIdx.x < 128) {
        int c = c0 + threadIdx.x - 64;
        const float* t = xgt + ((size_t)b * KK + c) * 3;
        float x = t[0], y = t[1], z = t[2];
        st[threadIdx.x - 64] = make_float4(x, y, z, x*x + y*y + z*z);
    }
    __syncthreads();
    float scale = 1.0f / (REG * (g_max[b] + 1e-8f));
    #pragma unroll
    for (int e = 0; e < 8; e++) {
        int idx = threadIdx.x + 256 * e;          // 0..2047
        int r = idx >> 5, cp = idx & 31;          // row, column-pair
        float4 S = ss[r];
        float4 T0 = st[cp*2], T1 = st[cp*2+1];
        float c0v = fmaxf(S.w + T0.w - 2.0f*(S.x*T0.x + S.y*T0.y + S.z*T0.z), 0.0f);
        float c1v = fmaxf(S.w + T1.w - 2.0f*(S.x*T1.x + S.y*T1.y + S.z*T1.z), 0.0f);
        unsigned short pk = float2_to_fp8x2(fast_exp_neg(c0v*scale),
                                            fast_exp_neg(c1v*scale));
        *(unsigned short*)(g_K8 + ((size_t)b * MM + r0 + r) * KK + c0 + cp*2) = pk;
    }
}

// ---------------- fused Sinkhorn iteration (fp8 + half2 math) ----------------
// Block: 64 rows x 2048 cols, 8 batches of 8 rows. Warp w owns cols
// [w*256,(w+1)*256); lane owns 8 (one uint2 of fp8 per row). Double-buffered.
// Row dots reduced two-at-a-time as packed half2 (5 shfl per 2 rows).
__global__ void __launch_bounds__(256, 3) k_fused() {
    __shared__ float sv[KK];
    __shared__ float sdot[8][8][8];          // [batch][row-in-batch][warp]
    int b   = blockIdx.x >> 6;
    int blk = blockIdx.x & 63;
    for (int j = threadIdx.x; j < KK; j += 256) sv[j] = g_v[b * KK + j];
    __syncthreads();
    int w = threadIdx.x >> 5, lane = threadIdx.x & 31;
    int col0 = w * 256 + lane * 8;
    float4 va = *(const float4*)(sv + col0);
    float4 vb = *(const float4*)(sv + col0 + 4);
    __half2 vh0 = __floats2half2_rn(va.x*16.0f, va.y*16.0f);
    __half2 vh1 = __floats2half2_rn(va.z*16.0f, va.w*16.0f);
    __half2 vh2 = __floats2half2_rn(vb.x*16.0f, vb.y*16.0f);
    __half2 vh3 = __floats2half2_rn(vb.z*16.0f, vb.w*16.0f);
    const __half2 hz = __floats2half2_rn(0.0f, 0.0f);

    float ct[8];
    #pragma unroll
    for (int i = 0; i < 8; i++) ct[i] = 0.0f;
    __half2 cth0 = hz, cth1 = hz, cth2 = hz, cth3 = hz;

    const unsigned char* Kbase =
        g_K8 + ((size_t)b * MM + blk * ROWS_PER_BLK) * KK + col0;

    uint2 qA[8], qB[8];
    #pragma unroll
    for (int r = 0; r < 8; r++)
        qA[r] = *(const uint2*)(Kbase + (size_t)r * KK);

    #pragma unroll 1
    for (int batch = 0; batch < NBATCH; batch++) {
        if (batch < NBATCH - 1) {
            const unsigned char* nb = Kbase + (size_t)(batch + 1) * 8 * KK;
            #pragma unroll
            for (int r = 0; r < 8; r++)
                qB[r] = *(const uint2*)(nb + (size_t)r * KK);
        }

        #pragma unroll
        for (int r = 0; r < 8; r += 2) {
            __half2 p0 = __hmul2(fp8x2_to_half2(qA[r].x), vh0);
            p0 = __hfma2(fp8x2_to_half2(qA[r].x >> 16), vh1, p0);
            p0 = __hfma2(fp8x2_to_half2(qA[r].y), vh2, p0);
            p0 = __hfma2(fp8x2_to_half2(qA[r].y >> 16), vh3, p0);
            __half2 p1 = __hmul2(fp8x2_to_half2(qA[r+1].x), vh0);
            p1 = __hfma2(fp8x2_to_half2(qA[r+1].x >> 16), vh1, p1);
            p1 = __hfma2(fp8x2_to_half2(qA[r+1].y), vh2, p1);
            p1 = __hfma2(fp8x2_to_half2(qA[r+1].y >> 16), vh3, p1);
            // pack the two row partial-dots and butterfly-reduce together
            __half2 d2 = __halves2half2(__hadd(__low2half(p0), __high2half(p0)),
                                        __hadd(__low2half(p1), __high2half(p1)));
            #pragma unroll
            for (int o = 16; o; o >>= 1) {
                unsigned int ud = *(unsigned int*)&d2;
                ud = __shfl_xor_sync(~0u, ud, o);
                d2 = __hadd2(d2, *(__half2*)&ud);
            }
            if (lane == r)     sdot[batch][r][w]   = __low2float(d2);
            if (lane == r + 1) sdot[batch][r+1][w] = __high2float(d2);
        }
        __syncthreads();

        float u_l = 0.0f;
        if (lane < 8) {
            float s = 0.0f;
            #pragma unroll
            for (int j = 0; j < 8; j++) s += sdot[batch][lane][j];
            // (a/y)^fi with a=1/M;  s = 16*y  =>  y*M = s*M/16
            u_l = exp2f(-FI * __log2f(s * ((float)MM * 0.0625f)));
            if (w == 0) g_u[b * MM + blk * ROWS_PER_BLK + batch * 8 + lane] = u_l;
        }
        #pragma unroll
        for (int r = 0; r < 8; r++) {
            float u = __shfl_sync(~0u, u_l, r);
            __half2 uh = __float2half2_rn(u * 16.0f);
            cth0 = __hfma2(fp8x2_to_half2(qA[r].x),       uh, cth0);
            cth1 = __hfma2(fp8x2_to_half2(qA[r].x >> 16), uh, cth1);
            cth2 = __hfma2(fp8x2_to_half2(qA[r].y),       uh, cth2);
            cth3 = __hfma2(fp8x2_to_half2(qA[r].y >> 16), uh, cth3);
            if (r == 3 || r == 7) {               // flush half partials -> fp32
                float2 c;
                c = __half22float2(cth0); ct[0] += c.x*0.0625f; ct[1] += c.y*0.0625f;
                c = __half22float2(cth1); ct[2] += c.x*0.0625f; ct[3] += c.y*0.0625f;
                c = __half22float2(cth2); ct[4] += c.x*0.0625f; ct[5] += c.y*0.0625f;
                c = __half22float2(cth3); ct[6] += c.x*0.0625f; ct[7] += c.y*0.0625f;
                cth0 = hz; cth1 = hz; cth2 = hz; cth3 = hz;
            }
        }
        #pragma unroll
        for (int r = 0; r < 8; r++) qA[r] = qB[r];
    }

    float* dst = g_ctp + ((size_t)(b * NPART + blk)) * KK + col0;
    *(float4*)dst       = make_float4(ct[0], ct[1], ct[2], ct[3]);
    *(float4*)(dst + 4) = make_float4(ct[4], ct[5], ct[6], ct[7]);
}

// ---------------- finish v-update: reduce partials, v = (b/ct)^fi -----------
__global__ void __launch_bounds__(256) k_vfix() {
    int b  = blockIdx.x >> 3;               // 8 column-chunks per batch
    int c  = (blockIdx.x & 7) * 256 + threadIdx.x;
    const float* base = g_ctp + (size_t)b * NPART * KK + c;
    float acc = 0.0f;
    #pragma unroll 8
    for (int p = 0; p < NPART; p++) acc += base[(size_t)p * KK];
    g_v[b * KK + c] = exp2f(-FI * __log2f(acc * (float)KK));  // (b/ct)^fi
}

// ---------------- final: pi-derived quantities + loss partials ---------------
__global__ void __launch_bounds__(256) k_final(const float* __restrict__ x0,
                                               const float* __restrict__ xgt,
                                               const float* __restrict__ vpred,
                                               const float* __restrict__ alpha) {
    __shared__ float4 sc[KK];          // {v_j, t_x, t_y, t_z}
    __shared__ float  red[8][3];
    int b   = blockIdx.x / (MM / 8);
    int row = (blockIdx.x % (MM / 8)) * 8 + (threadIdx.x >> 5);
    const float* tg = xgt + (size_t)b * KK * 3;
    for (int j = threadIdx.x; j < KK; j += 256)
        sc[j] = make_float4(g_v[b * KK + j], tg[j*3], tg[j*3+1], tg[j*3+2]);
    __syncthreads();
    int w = threadIdx.x >> 5, lane = threadIdx.x & 31;
    const unsigned char* Kr = g_K8 + ((size_t)b * MM + row) * KK;
    float y = 0.0f, wx = 0.0f, wy = 0.0f, wz = 0.0f;
    #pragma unroll
    for (int k = 0; k < 8; k++) {
        uint2 q = *(const uint2*)(Kr + (size_t)(k * 32 + lane) * 8);
        int jb = (k * 32 + lane) * 8;
        float2 ff[4];
        ff[0] = fp8x2_to_float2((unsigned short)(q.x & 0xFFFF));
        ff[1] = fp8x2_to_float2((unsigned short)(q.x >> 16));
        ff[2] = fp8x2_to_float2((unsigned short)(q.y & 0xFFFF));
        ff[3] = fp8x2_to_float2((unsigned short)(q.y >> 16));
        #pragma unroll
        for (int p = 0; p < 4; p++) {
            float4 cA = sc[jb + 2*p];
            float4 cB = sc[jb + 2*p + 1];
            float kv = ff[p].x * cA.x; y += kv; wx += kv*cA.y; wy += kv*cA.z; wz += kv*cA.w;
            kv       = ff[p].y * cB.x; y += kv; wx += kv*cB.y; wy += kv*cB.z; wz += kv*cB.w;
        }
    }
    #pragma unroll
    for (int o = 16; o; o >>= 1) {
        y  += __shfl_xor_sync(~0u, y,  o);
        wx += __shfl_xor_sync(~0u, wx, o);
        wy += __shfl_xor_sync(~0u, wy, o);
        wz += __shfl_xor_sync(~0u, wz, o);
    }
    if (lane == 0) {
        float u    = g_u[b * MM + row];
        float sm   = u * y;                                  // pi row sum
        float surv = fminf(fmaxf(sm * (float)MM, 0.0f), 1.0f);
        float inv  = u / (sm + 1e-8f);
        const float* s  = x0    + ((size_t)b * MM + row) * 3;
        const float* vp = vpred + ((size_t)b * MM + row) * 3;
        float dx = (vp[0] - (wx * inv - s[0])) * surv;
        float dy = (vp[1] - (wy * inv - s[1])) * surv;
        float dz = (vp[2] - (wz * inv - s[2])) * surv;
        float ssq = dx*dx + dy*dy + dz*dz;
        float xv  = alpha[b * MM + row];
        float bce = fmaxf(xv, 0.0f) - xv * surv + log1pf(__expf(-fabsf(xv)));
        red[w][0] = ssq; red[w][1] = surv; red[w][2] = bce;
    }
    __syncthreads();
    if (threadIdx.x == 0) {
        float a0 = 0, a1 = 0, a2 = 0;
        #pragma unroll
        for (int i = 0; i < 8; i++) { a0 += red[i][0]; a1 += red[i][1]; a2 += red[i][2]; }
        atomicAdd(&g_acc[0], a0);
        atomicAdd(&g_acc[1], a1);
        atomicAdd(&g_acc[2], a2);
    }
}

__global__ void k_out(float* out) {
    out[0] = g_acc[0] / fmaxf(g_acc[1], 1.0f) + g_acc[2] * (1.0f / (float)(BB * MM));
}

// ---------------- launch -----------------------------------------------------
extern "C" void kernel_launch(void* const* d_in, const int* in_sizes, int n_in,
                              void* d_out, int out_size) {
    const float* x0  = (const float*)d_in[0];   // [B,M,3]
    const float* xgt = (const float*)d_in[1];   // [B,K,3]
    const float* vp  = (const float*)d_in[2];   // [B,M,3]
    const float* al  = (const float*)d_in[3];   // [B,M,1]
    // d_in[4] = t : unused by the reference loss
    (void)in_sizes; (void)n_in; (void)out_size;

    k_init<<<(BB * KK + 255) / 256, 256>>>();
    k_max<<<BB * MM / 8, 256>>>(x0, xgt);
    dim3 gb(KK / 64, MM / 64, BB);
    k_build<<<gb, 256>>>(x0, xgt);
    for (int it = 0; it < NITER; it++) {
        k_fused<<<BB * BLKS_PER_B, 256>>>();
        k_vfix<<<BB * 8, 256>>>();
    }
    k_final<<<BB * MM / 8, 256>>>(x0, xgt, vp, al);
    k_out<<<1, 1>>>((float*)d_out);
}

// round 13
// speedup vs baseline: 1.2886x; 1.2886x over previous
#include <cuda_runtime.h>
#include <cuda_fp16.h>

// Problem constants (fixed by setup_inputs)
#define BB 8
#define MM 4096
#define KK 2048
#define NITER 28
#define FI (5.0f/6.0f)     // reg_m / (reg_m + reg) = 0.5/0.6
#define REG 0.1f

// fused-kernel geometry: 256 thr (8 warps), 128 rows per block (16 batches
// of 8), warp owns a 256-column strip, lane owns 8 contiguous columns.
#define ROWS_PER_BLK 128
#define NBATCH       (ROWS_PER_BLK/8)       // 16
#define BLKS_PER_B   (MM/ROWS_PER_BLK)      // 32 blocks per batch
#define NPART        BLKS_PER_B             // 32 column partials per batch

// ---------------- scratch (device globals; no runtime allocation) ----------
__device__ unsigned char g_K8[(size_t)BB*MM*KK];   // e4m3 K, [b][m][k]
__device__ float  g_ctp[(size_t)BB*NPART*KK];      // per-block column partials
__device__ float  g_u [BB*MM];
__device__ float  g_v [BB*KK];
__device__ float  g_max[BB];
__device__ float  g_acc[3];                        // ssq, sum_survival, sum_bce

// ---------------- fp8 helpers ------------------------------------------------
__device__ __forceinline__ float2 fp8x2_to_float2(unsigned short s) {
    unsigned int h;
    asm("cvt.rn.f16x2.e4m3x2 %0, %1;" : "=r"(h) : "h"(s));
    return __half22float2(*(__half2*)&h);
}
__device__ __forceinline__ __half2 fp8x2_to_half2(unsigned int s) {
    unsigned int h;
    asm("cvt.rn.f16x2.e4m3x2 %0, %1;" : "=r"(h) : "h"((unsigned short)s));
    return *(__half2*)&h;
}
__device__ __forceinline__ unsigned short float2_to_fp8x2(float lo, float hi) {
    unsigned short s;
    asm("cvt.rn.satfinite.e4m3x2.f32 %0, %1, %2;" : "=h"(s) : "f"(hi), "f"(lo));
    return s;  // first source -> high byte, second -> low byte
}

// ---------------- fast exp(-x) on the FMA pipe (x >= 0, x <= ~15) -----------
__device__ __forceinline__ float fast_exp_neg(float x) {
    float t  = -x * 1.4426950408889634f;          // log2(e)
    float fl = floorf(t);
    float f  = t - fl;                            // [0,1)
    float g  = f * 0.6931471805599453f;           // ln2 * f
    float p = 1.0f + g*(1.0f + g*(0.5f + g*(0.16666667f +
              g*(0.041666667f + g*(0.0083333333f + g*0.0013888889f)))));
    int i = (int)fl;
    return p * __int_as_float((i + 127) << 23);
}

// ---------------- init ------------------------------------------------------
__global__ void k_init() {
    int i = blockIdx.x * blockDim.x + threadIdx.x;
    if (i < BB * KK) g_v[i] = 1.0f / (float)KK;
    if (i < BB)      g_max[i] = 0.0f;
    if (i < 3)       g_acc[i] = 0.0f;
}

// ---------------- per-batch max of cost matrix ------------------------------
__global__ void __launch_bounds__(256) k_max(const float* __restrict__ x0,
                                             const float* __restrict__ xgt) {
    __shared__ float4 st[KK];
    __shared__ float  wm[8];
    int b    = blockIdx.x / (MM / 8);
    int row0 = (blockIdx.x % (MM / 8)) * 8;
    const float* tg = xgt + (size_t)b * KK * 3;
    for (int j = threadIdx.x; j < KK; j += 256) {
        float tx = tg[j*3], ty = tg[j*3+1], tz = tg[j*3+2];
        st[j] = make_float4(tx, ty, tz, tx*tx + ty*ty + tz*tz);
    }
    __syncthreads();
    int w = threadIdx.x >> 5, lane = threadIdx.x & 31;
    int row = row0 + w;
    const float* s = x0 + ((size_t)b * MM + row) * 3;
    float sx = s[0], sy = s[1], sz = s[2];
    float s2 = sx*sx + sy*sy + sz*sz;
    float mx = 0.0f;
    for (int j = lane; j < KK; j += 32) {
        float4 t = st[j];
        float c = s2 + t.w - 2.0f * (sx*t.x + sy*t.y + sz*t.z);
        mx = fmaxf(mx, c);
    }
    #pragma unroll
    for (int o = 16; o; o >>= 1) mx = fmaxf(mx, __shfl_xor_sync(~0u, mx, o));
    if (lane == 0) wm[w] = mx;
    __syncthreads();
    if (threadIdx.x == 0) {
        float m = wm[0];
        #pragma unroll
        for (int i = 1; i < 8; i++) m = fmaxf(m, wm[i]);
        atomicMax((int*)&g_max[b], __float_as_int(m));  // nonneg floats: int order ok
    }
}

// ---------------- build K (e4m3), FMA-pipe exp ------------------------------
__global__ void __launch_bounds__(256) k_build(const float* __restrict__ x0,
                                               const float* __restrict__ xgt) {
    __shared__ float4 ss[64], st[64];
    int b  = blockIdx.z;
    int r0 = blockIdx.y * 64, c0 = blockIdx.x * 64;
    if (threadIdx.x < 64) {
        int r = r0 + threadIdx.x;
        const float* s = x0 + ((size_t)b * MM + r) * 3;
        float x = s[0], y = s[1], z = s[2];
        ss[threadIdx.x] = make_float4(x, y, z, x*x + y*y + z*z);
    } else if (threadIdx.x < 128) {
        int c = c0 + threadIdx.x - 64;
        const float* t = xgt + ((size_t)b * KK + c) * 3;
        float x = t[0], y = t[1], z = t[2];
        st[threadIdx.x - 64] = make_float4(x, y, z, x*x + y*y + z*z);
    }
    __syncthreads();
    float scale = 1.0f / (REG * (g_max[b] + 1e-8f));
    #pragma unroll
    for (int e = 0; e < 8; e++) {
        int idx = threadIdx.x + 256 * e;          // 0..2047
        int r = idx >> 5, cp = idx & 31;          // row, column-pair
        float4 S = ss[r];
        float4 T0 = st[cp*2], T1 = st[cp*2+1];
        float c0v = fmaxf(S.w + T0.w - 2.0f*(S.x*T0.x + S.y*T0.y + S.z*T0.z), 0.0f);
        float c1v = fmaxf(S.w + T1.w - 2.0f*(S.x*T1.x + S.y*T1.y + S.z*T1.z), 0.0f);
        unsigned short pk = float2_to_fp8x2(fast_exp_neg(c0v*scale),
                                            fast_exp_neg(c1v*scale));
        *(unsigned short*)(g_K8 + ((size_t)b * MM + r0 + r) * KK + c0 + cp*2) = pk;
    }
}

// ---------------- fused Sinkhorn iteration (fp8 + half2, decode-once) --------
// Block: 128 rows x 2048 cols, 16 batches of 8 rows. Warp w owns cols
// [w*256,(w+1)*256); lane owns 8 (one uint2 of fp8 per row). Double-buffered
// loads; fp8 decoded ONCE per batch into half2 regs, reused in both phases.
__global__ void __launch_bounds__(256, 2) k_fused() {
    __shared__ float sv[KK];
    __shared__ float sdot[8][8][8];          // [batch&7][row-in-batch][warp]
    int b   = blockIdx.x >> 5;
    int blk = blockIdx.x & 31;
    for (int j = threadIdx.x; j < KK; j += 256) sv[j] = g_v[b * KK + j];
    __syncthreads();
    int w = threadIdx.x >> 5, lane = threadIdx.x & 31;
    int col0 = w * 256 + lane * 8;
    float4 va = *(const float4*)(sv + col0);
    float4 vb = *(const float4*)(sv + col0 + 4);
    __half2 vh0 = __floats2half2_rn(va.x*16.0f, va.y*16.0f);
    __half2 vh1 = __floats2half2_rn(va.z*16.0f, va.w*16.0f);
    __half2 vh2 = __floats2half2_rn(vb.x*16.0f, vb.y*16.0f);
    __half2 vh3 = __floats2half2_rn(vb.z*16.0f, vb.w*16.0f);
    const __half2 hz = __floats2half2_rn(0.0f, 0.0f);

    float ct[8];
    #pragma unroll
    for (int i = 0; i < 8; i++) ct[i] = 0.0f;
    __half2 cth0 = hz, cth1 = hz, cth2 = hz, cth3 = hz;

    const unsigned char* Kbase =
        g_K8 + ((size_t)b * MM + blk * ROWS_PER_BLK) * KK + col0;

    uint2 qA[8], qB[8];
    #pragma unroll
    for (int r = 0; r < 8; r++)
        qA[r] = *(const uint2*)(Kbase + (size_t)r * KK);

    #pragma unroll 1
    for (int batch = 0; batch < NBATCH; batch++) {
        if (batch < NBATCH - 1) {
            const unsigned char* nb = Kbase + (size_t)(batch + 1) * 8 * KK;
            #pragma unroll
            for (int r = 0; r < 8; r++)
                qB[r] = *(const uint2*)(nb + (size_t)r * KK);
        }

        // decode once per batch; reuse in dot and accumulate phases
        __half2 f[8][4];
        #pragma unroll
        for (int r = 0; r < 8; r++) {
            f[r][0] = fp8x2_to_half2(qA[r].x);
            f[r][1] = fp8x2_to_half2(qA[r].x >> 16);
            f[r][2] = fp8x2_to_half2(qA[r].y);
            f[r][3] = fp8x2_to_half2(qA[r].y >> 16);
        }

        int slot = batch & 7;
        #pragma unroll
        for (int r = 0; r < 8; r++) {
            __half2 p = __hmul2(f[r][0], vh0);
            p = __hfma2(f[r][1], vh1, p);
            p = __hfma2(f[r][2], vh2, p);
            p = __hfma2(f[r][3], vh3, p);
            float2 pf = __half22float2(p);
            float d = pf.x + pf.y;                 // carries x16 from vh
            #pragma unroll
            for (int o = 16; o; o >>= 1) d += __shfl_xor_sync(~0u, d, o);
            if (lane == r) sdot[slot][r][w] = d;
        }
        __syncthreads();

        float u_l = 0.0f;
        if (lane < 8) {
            float s = 0.0f;
            #pragma unroll
            for (int j = 0; j < 8; j++) s += sdot[slot][lane][j];
            // (a/y)^fi with a=1/M;  s = 16*y  =>  y*M = s*M/16
            u_l = exp2f(-FI * __log2f(s * ((float)MM * 0.0625f)));
            if (w == 0) g_u[b * MM + blk * ROWS_PER_BLK + batch * 8 + lane] = u_l;
        }
        #pragma unroll
        for (int r = 0; r < 8; r++) {
            float u = __shfl_sync(~0u, u_l, r);
            __half2 uh = __float2half2_rn(u * 16.0f);
            cth0 = __hfma2(f[r][0], uh, cth0);
            cth1 = __hfma2(f[r][1], uh, cth1);
            cth2 = __hfma2(f[r][2], uh, cth2);
            cth3 = __hfma2(f[r][3], uh, cth3);
            if (r == 3 || r == 7) {               // flush half partials -> fp32
                float2 c;
                c = __half22float2(cth0); ct[0] += c.x*0.0625f; ct[1] += c.y*0.0625f;
                c = __half22float2(cth1); ct[2] += c.x*0.0625f; ct[3] += c.y*0.0625f;
                c = __half22float2(cth2); ct[4] += c.x*0.0625f; ct[5] += c.y*0.0625f;
                c = __half22float2(cth3); ct[6] += c.x*0.0625f; ct[7] += c.y*0.0625f;
                cth0 = hz; cth1 = hz; cth2 = hz; cth3 = hz;
            }
        }
        #pragma unroll
        for (int r = 0; r < 8; r++) qA[r] = qB[r];
        // slot reuse (batch&7) is safe: >=7 barriers between a slot's reads
        // and its next write
    }

    float* dst = g_ctp + ((size_t)(b * NPART + blk)) * KK + col0;
    *(float4*)dst       = make_float4(ct[0], ct[1], ct[2], ct[3]);
    *(float4*)(dst + 4) = make_float4(ct[4], ct[5], ct[6], ct[7]);
}

// ---------------- finish v-update: reduce partials, v = (b/ct)^fi -----------
__global__ void __launch_bounds__(256) k_vfix() {
    int b  = blockIdx.x >> 3;               // 8 column-chunks per batch
    int c  = (blockIdx.x & 7) * 256 + threadIdx.x;
    const float* base = g_ctp + (size_t)b * NPART * KK + c;
    float acc = 0.0f;
    #pragma unroll
    for (int p = 0; p < NPART; p++) acc += base[(size_t)p * KK];
    g_v[b * KK + c] = exp2f(-FI * __log2f(acc * (float)KK));  // (b/ct)^fi
}

// ---------------- final: pi-derived quantities + loss partials ---------------
__global__ void __launch_bounds__(256) k_final(const float* __restrict__ x0,
                                               const float* __restrict__ xgt,
                                               const float* __restrict__ vpred,
                                               const float* __restrict__ alpha) {
    __shared__ float4 sc[KK];          // {v_j, t_x, t_y, t_z}
    __shared__ float  red[8][3];
    int b   = blockIdx.x / (MM / 8);
    int row = (blockIdx.x % (MM / 8)) * 8 + (threadIdx.x >> 5);
    const float* tg = xgt + (size_t)b * KK * 3;
    for (int j = threadIdx.x; j < KK; j += 256)
        sc[j] = make_float4(g_v[b * KK + j], tg[j*3], tg[j*3+1], tg[j*3+2]);
    __syncthreads();
    int w = threadIdx.x >> 5, lane = threadIdx.x & 31;
    const unsigned char* Kr = g_K8 + ((size_t)b * MM + row) * KK;
    float y = 0.0f, wx = 0.0f, wy = 0.0f, wz = 0.0f;
    #pragma unroll
    for (int k = 0; k < 8; k++) {
        uint2 q = *(const uint2*)(Kr + (size_t)(k * 32 + lane) * 8);
        int jb = (k * 32 + lane) * 8;
        float2 ff[4];
        ff[0] = fp8x2_to_float2((unsigned short)(q.x & 0xFFFF));
        ff[1] = fp8x2_to_float2((unsigned short)(q.x >> 16));
        ff[2] = fp8x2_to_float2((unsigned short)(q.y & 0xFFFF));
        ff[3] = fp8x2_to_float2((unsigned short)(q.y >> 16));
        #pragma unroll
        for (int p = 0; p < 4; p++) {
            float4 cA = sc[jb + 2*p];
            float4 cB = sc[jb + 2*p + 1];
            float kv = ff[p].x * cA.x; y += kv; wx += kv*cA.y; wy += kv*cA.z; wz += kv*cA.w;
            kv       = ff[p].y * cB.x; y += kv; wx += kv*cB.y; wy += kv*cB.z; wz += kv*cB.w;
        }
    }
    #pragma unroll
    for (int o = 16; o; o >>= 1) {
        y  += __shfl_xor_sync(~0u, y,  o);
        wx += __shfl_xor_sync(~0u, wx, o);
        wy += __shfl_xor_sync(~0u, wy, o);
        wz += __shfl_xor_sync(~0u, wz, o);
    }
    if (lane == 0) {
        float u    = g_u[b * MM + row];
        float sm   = u * y;                                  // pi row sum
        float surv = fminf(fmaxf(sm * (float)MM, 0.0f), 1.0f);
        float inv  = u / (sm + 1e-8f);
        const float* s  = x0    + ((size_t)b * MM + row) * 3;
        const float* vp = vpred + ((size_t)b * MM + row) * 3;
        float dx = (vp[0] - (wx * inv - s[0])) * surv;
        float dy = (vp[1] - (wy * inv - s[1])) * surv;
        float dz = (vp[2] - (wz * inv - s[2])) * surv;
        float ssq = dx*dx + dy*dy + dz*dz;
        float xv  = alpha[b * MM + row];
        float bce = fmaxf(xv, 0.0f) - xv * surv + log1pf(__expf(-fabsf(xv)));
        red[w][0] = ssq; red[w][1] = surv; red[w][2] = bce;
    }
    __syncthreads();
    if (threadIdx.x == 0) {
        float a0 = 0, a1 = 0, a2 = 0;
        #pragma unroll
        for (int i = 0; i < 8; i++) { a0 += red[i][0]; a1 += red[i][1]; a2 += red[i][2]; }
        atomicAdd(&g_acc[0], a0);
        atomicAdd(&g_acc[1], a1);
        atomicAdd(&g_acc[2], a2);
    }
}

__global__ void k_out(float* out) {
    out[0] = g_acc[0] / fmaxf(g_acc[1], 1.0f) + g_acc[2] * (1.0f / (float)(BB * MM));
}

// ---------------- launch -----------------------------------------------------
extern "C" void kernel_launch(void* const* d_in, const int* in_sizes, int n_in,
                              void* d_out, int out_size) {
    const float* x0  = (const float*)d_in[0];   // [B,M,3]
    const float* xgt = (const float*)d_in[1];   // [B,K,3]
    const float* vp  = (const float*)d_in[2];   // [B,M,3]
    const float* al  = (const float*)d_in[3];   // [B,M,1]
    // d_in[4] = t : unused by the reference loss
    (void)in_sizes; (void)n_in; (void)out_size;

    k_init<<<(BB * KK + 255) / 256, 256>>>();
    k_max<<<BB * MM / 8, 256>>>(x0, xgt);
    dim3 gb(KK / 64, MM / 64, BB);
    k_build<<<gb, 256>>>(x0, xgt);
    for (int it = 0; it < NITER; it++) {
        k_fused<<<BB * BLKS_PER_B, 256>>>();
        k_vfix<<<BB * 8, 256>>>();
    }
    k_final<<<BB * MM / 8, 256>>>(x0, xgt, vp, al);
    k_out<<<1, 1>>>((float*)d_out);
}

// round 14
// speedup vs baseline: 1.4156x; 1.0985x over previous
#include <cuda_runtime.h>
#include <cuda_fp16.h>

// Problem constants (fixed by setup_inputs)
#define BB 8
#define MM 4096
#define KK 2048
#define NITER 20
#define FI (5.0f/6.0f)     // reg_m / (reg_m + reg) = 0.5/0.6
#define REG 0.1f

// fused-kernel geometry: 256 thr (8 warps), 128 rows per block (16 batches
// of 8), warp owns a 256-column strip, lane owns 8 contiguous columns.
#define ROWS_PER_BLK 128
#define NBATCH       (ROWS_PER_BLK/8)       // 16
#define BLKS_PER_B   (MM/ROWS_PER_BLK)      // 32 blocks per batch
#define NPART        BLKS_PER_B             // 32 column partials per batch

// ---------------- scratch (device globals; no runtime allocation) ----------
__device__ unsigned char g_K8[(size_t)BB*MM*KK];   // e4m3 K, [b][m][k]
__device__ float  g_ctp[(size_t)BB*NPART*KK];      // per-block column partials
__device__ float  g_u [BB*MM];
__device__ float  g_v [BB*KK];
__device__ float  g_max[BB];
__device__ float  g_acc[3];                        // ssq, sum_survival, sum_bce

// ---------------- fp8 helpers ------------------------------------------------
__device__ __forceinline__ float2 fp8x2_to_float2(unsigned short s) {
    unsigned int h;
    asm("cvt.rn.f16x2.e4m3x2 %0, %1;" : "=r"(h) : "h"(s));
    return __half22float2(*(__half2*)&h);
}
__device__ __forceinline__ __half2 fp8x2_to_half2(unsigned int s) {
    unsigned int h;
    asm("cvt.rn.f16x2.e4m3x2 %0, %1;" : "=r"(h) : "h"((unsigned short)s));
    return *(__half2*)&h;
}
__device__ __forceinline__ unsigned short float2_to_fp8x2(float lo, float hi) {
    unsigned short s;
    asm("cvt.rn.satfinite.e4m3x2.f32 %0, %1, %2;" : "=h"(s) : "f"(hi), "f"(lo));
    return s;  // first source -> high byte, second -> low byte
}

// ---------------- fast exp(-x) on the FMA pipe (x >= 0, x <= ~15) -----------
__device__ __forceinline__ float fast_exp_neg(float x) {
    float t  = -x * 1.4426950408889634f;          // log2(e)
    float fl = floorf(t);
    float f  = t - fl;                            // [0,1)
    float g  = f * 0.6931471805599453f;           // ln2 * f
    float p = 1.0f + g*(1.0f + g*(0.5f + g*(0.16666667f +
              g*(0.041666667f + g*(0.0083333333f + g*0.0013888889f)))));
    int i = (int)fl;
    return p * __int_as_float((i + 127) << 23);
}

// ---------------- init ------------------------------------------------------
__global__ void k_init() {
    int i = blockIdx.x * blockDim.x + threadIdx.x;
    if (i < BB * KK) g_v[i] = 1.0f / (float)KK;
    if (i < BB)      g_max[i] = 0.0f;
    if (i < 3)       g_acc[i] = 0.0f;
}

// ---------------- per-batch max of cost matrix ------------------------------
__global__ void __launch_bounds__(256) k_max(const float* __restrict__ x0,
                                             const float* __restrict__ xgt) {
    __shared__ float4 st[KK];
    __shared__ float  wm[8];
    int b    = blockIdx.x / (MM / 8);
    int row0 = (blockIdx.x % (MM / 8)) * 8;
    const float* tg = xgt + (size_t)b * KK * 3;
    for (int j = threadIdx.x; j < KK; j += 256) {
        float tx = tg[j*3], ty = tg[j*3+1], tz = tg[j*3+2];
        st[j] = make_float4(tx, ty, tz, tx*tx + ty*ty + tz*tz);
    }
    __syncthreads();
    int w = threadIdx.x >> 5, lane = threadIdx.x & 31;
    int row = row0 + w;
    const float* s = x0 + ((size_t)b * MM + row) * 3;
    float sx = s[0], sy = s[1], sz = s[2];
    float s2 = sx*sx + sy*sy + sz*sz;
    float mx = 0.0f;
    for (int j = lane; j < KK; j += 32) {
        float4 t = st[j];
        float c = s2 + t.w - 2.0f * (sx*t.x + sy*t.y + sz*t.z);
        mx = fmaxf(mx, c);
    }
    #pragma unroll
    for (int o = 16; o; o >>= 1) mx = fmaxf(mx, __shfl_xor_sync(~0u, mx, o));
    if (lane == 0) wm[w] = mx;
    __syncthreads();
    if (threadIdx.x == 0) {
        float m = wm[0];
        #pragma unroll
        for (int i = 1; i < 8; i++) m = fmaxf(m, wm[i]);
        atomicMax((int*)&g_max[b], __float_as_int(m));  // nonneg floats: int order ok
    }
}

// ---------------- build K (e4m3), FMA-pipe exp ------------------------------
__global__ void __launch_bounds__(256) k_build(const float* __restrict__ x0,
                                               const float* __restrict__ xgt) {
    __shared__ float4 ss[64], st[64];
    int b  = blockIdx.z;
    int r0 = blockIdx.y * 64, c0 = blockIdx.x * 64;
    if (threadIdx.x < 64) {
        int r = r0 + threadIdx.x;
        const float* s = x0 + ((size_t)b * MM + r) * 3;
        float x = s[0], y = s[1], z = s[2];
        ss[threadIdx.x] = make_float4(x, y, z, x*x + y*y + z*z);
    } else if (threadIdx.x < 128) {
        int c = c0 + threadIdx.x - 64;
        const float* t = xgt + ((size_t)b * KK + c) * 3;
        float x = t[0], y = t[1], z = t[2];
        st[threadIdx.x - 64] = make_float4(x, y, z, x*x + y*y + z*z);
    }
    __syncthreads();
    float scale = 1.0f / (REG * (g_max[b] + 1e-8f));
    #pragma unroll
    for (int e = 0; e < 8; e++) {
        int idx = threadIdx.x + 256 * e;          // 0..2047
        int r = idx >> 5, cp = idx & 31;          // row, column-pair
        float4 S = ss[r];
        float4 T0 = st[cp*2], T1 = st[cp*2+1];
        float c0v = fmaxf(S.w + T0.w - 2.0f*(S.x*T0.x + S.y*T0.y + S.z*T0.z), 0.0f);
        float c1v = fmaxf(S.w + T1.w - 2.0f*(S.x*T1.x + S.y*T1.y + S.z*T1.z), 0.0f);
        unsigned short pk = float2_to_fp8x2(fast_exp_neg(c0v*scale),
                                            fast_exp_neg(c1v*scale));
        *(unsigned short*)(g_K8 + ((size_t)b * MM + r0 + r) * KK + c0 + cp*2) = pk;
    }
}

// ---------------- fused Sinkhorn iteration (fp8 + half2, decode-once) --------
// Block: 128 rows x 2048 cols, 16 batches of 8 rows. Warp w owns cols
// [w*256,(w+1)*256); lane owns 8 (one uint2 of fp8 per row). Double-buffered
// loads; fp8 decoded ONCE per batch; row dots reduced two-at-a-time as
// packed half2 (5 shfl per 2 rows).
__global__ void __launch_bounds__(256, 2) k_fused() {
    __shared__ float sv[KK];
    __shared__ float sdot[8][8][8];          // [batch&7][row-in-batch][warp]
    int b   = blockIdx.x >> 5;
    int blk = blockIdx.x & 31;
    for (int j = threadIdx.x; j < KK; j += 256) sv[j] = g_v[b * KK + j];
    __syncthreads();
    int w = threadIdx.x >> 5, lane = threadIdx.x & 31;
    int col0 = w * 256 + lane * 8;
    float4 va = *(const float4*)(sv + col0);
    float4 vb = *(const float4*)(sv + col0 + 4);
    __half2 vh0 = __floats2half2_rn(va.x*16.0f, va.y*16.0f);
    __half2 vh1 = __floats2half2_rn(va.z*16.0f, va.w*16.0f);
    __half2 vh2 = __floats2half2_rn(vb.x*16.0f, vb.y*16.0f);
    __half2 vh3 = __floats2half2_rn(vb.z*16.0f, vb.w*16.0f);
    const __half2 hz = __floats2half2_rn(0.0f, 0.0f);

    float ct[8];
    #pragma unroll
    for (int i = 0; i < 8; i++) ct[i] = 0.0f;
    __half2 cth0 = hz, cth1 = hz, cth2 = hz, cth3 = hz;

    const unsigned char* Kbase =
        g_K8 + ((size_t)b * MM + blk * ROWS_PER_BLK) * KK + col0;

    uint2 qA[8], qB[8];
    #pragma unroll
    for (int r = 0; r < 8; r++)
        qA[r] = *(const uint2*)(Kbase + (size_t)r * KK);

    #pragma unroll 1
    for (int batch = 0; batch < NBATCH; batch++) {
        if (batch < NBATCH - 1) {
            const unsigned char* nb = Kbase + (size_t)(batch + 1) * 8 * KK;
            #pragma unroll
            for (int r = 0; r < 8; r++)
                qB[r] = *(const uint2*)(nb + (size_t)r * KK);
        }

        // decode once per batch; reuse in dot and accumulate phases
        __half2 f[8][4];
        #pragma unroll
        for (int r = 0; r < 8; r++) {
            f[r][0] = fp8x2_to_half2(qA[r].x);
            f[r][1] = fp8x2_to_half2(qA[r].x >> 16);
            f[r][2] = fp8x2_to_half2(qA[r].y);
            f[r][3] = fp8x2_to_half2(qA[r].y >> 16);
        }

        int slot = batch & 7;
        #pragma unroll
        for (int r = 0; r < 8; r += 2) {
            __half2 p0 = __hmul2(f[r][0], vh0);
            p0 = __hfma2(f[r][1], vh1, p0);
            p0 = __hfma2(f[r][2], vh2, p0);
            p0 = __hfma2(f[r][3], vh3, p0);
            __half2 p1 = __hmul2(f[r+1][0], vh0);
            p1 = __hfma2(f[r+1][1], vh1, p1);
            p1 = __hfma2(f[r+1][2], vh2, p1);
            p1 = __hfma2(f[r+1][3], vh3, p1);
            // pack the two row partial-dots, butterfly-reduce together
            __half2 d2 = __halves2half2(__hadd(__low2half(p0), __high2half(p0)),
                                        __hadd(__low2half(p1), __high2half(p1)));
            #pragma unroll
            for (int o = 16; o; o >>= 1) {
                unsigned int ud = *(unsigned int*)&d2;
                ud = __shfl_xor_sync(~0u, ud, o);
                d2 = __hadd2(d2, *(__half2*)&ud);
            }
            if (lane == r)     sdot[slot][r][w]   = __low2float(d2);
            if (lane == r + 1) sdot[slot][r+1][w] = __high2float(d2);
        }
        __syncthreads();

        float u_l = 0.0f;
        if (lane < 8) {
            float s = 0.0f;
            #pragma unroll
            for (int j = 0; j < 8; j++) s += sdot[slot][lane][j];
            // (a/y)^fi with a=1/M;  s = 16*y  =>  y*M = s*M/16
            u_l = exp2f(-FI * __log2f(s * ((float)MM * 0.0625f)));
            if (w == 0) g_u[b * MM + blk * ROWS_PER_BLK + batch * 8 + lane] = u_l;
        }
        #pragma unroll
        for (int r = 0; r < 8; r++) {
            float u = __shfl_sync(~0u, u_l, r);
            __half2 uh = __float2half2_rn(u * 16.0f);
            cth0 = __hfma2(f[r][0], uh, cth0);
            cth1 = __hfma2(f[r][1], uh, cth1);
            cth2 = __hfma2(f[r][2], uh, cth2);
            cth3 = __hfma2(f[r][3], uh, cth3);
            if (r == 3 || r == 7) {               // flush half partials -> fp32
                float2 c;
                c = __half22float2(cth0); ct[0] += c.x*0.0625f; ct[1] += c.y*0.0625f;
                c = __half22float2(cth1); ct[2] += c.x*0.0625f; ct[3] += c.y*0.0625f;
                c = __half22float2(cth2); ct[4] += c.x*0.0625f; ct[5] += c.y*0.0625f;
                c = __half22float2(cth3); ct[6] += c.x*0.0625f; ct[7] += c.y*0.0625f;
                cth0 = hz; cth1 = hz; cth2 = hz; cth3 = hz;
            }
        }
        #pragma unroll
        for (int r = 0; r < 8; r++) qA[r] = qB[r];
        // slot reuse (batch&7) is safe: >=7 barriers between a slot's reads
        // and its next write
    }

    float* dst = g_ctp + ((size_t)(b * NPART + blk)) * KK + col0;
    *(float4*)dst       = make_float4(ct[0], ct[1], ct[2], ct[3]);
    *(float4*)(dst + 4) = make_float4(ct[4], ct[5], ct[6], ct[7]);
}

// ---------------- finish v-update: reduce partials, v = (b/ct)^fi -----------
__global__ void __launch_bounds__(256) k_vfix() {
    int b  = blockIdx.x >> 3;               // 8 column-chunks per batch
    int c  = (blockIdx.x & 7) * 256 + threadIdx.x;
    const float* base = g_ctp + (size_t)b * NPART * KK + c;
    float acc = 0.0f;
    #pragma unroll
    for (int p = 0; p < NPART; p++) acc += base[(size_t)p * KK];
    g_v[b * KK + c] = exp2f(-FI * __log2f(acc * (float)KK));  // (b/ct)^fi
}

// ---------------- final: pi-derived quantities + loss partials ---------------
__global__ void __launch_bounds__(256) k_final(const float* __restrict__ x0,
                                               const float* __restrict__ xgt,
                                               const float* __restrict__ vpred,
                                               const float* __restrict__ alpha) {
    __shared__ float4 sc[KK];          // {v_j, t_x, t_y, t_z}
    __shared__ float  red[8][3];
    int b   = blockIdx.x / (MM / 8);
    int row = (blockIdx.x % (MM / 8)) * 8 + (threadIdx.x >> 5);
    const float* tg = xgt + (size_t)b * KK * 3;
    for (int j = threadIdx.x; j < KK; j += 256)
        sc[j] = make_float4(g_v[b * KK + j], tg[j*3], tg[j*3+1], tg[j*3+2]);
    __syncthreads();
    int w = threadIdx.x >> 5, lane = threadIdx.x & 31;
    const unsigned char* Kr = g_K8 + ((size_t)b * MM + row) * KK;
    float y = 0.0f, wx = 0.0f, wy = 0.0f, wz = 0.0f;
    #pragma unroll
    for (int k = 0; k < 8; k++) {
        uint2 q = *(const uint2*)(Kr + (size_t)(k * 32 + lane) * 8);
        int jb = (k * 32 + lane) * 8;
        float2 ff[4];
        ff[0] = fp8x2_to_float2((unsigned short)(q.x & 0xFFFF));
        ff[1] = fp8x2_to_float2((unsigned short)(q.x >> 16));
        ff[2] = fp8x2_to_float2((unsigned short)(q.y & 0xFFFF));
        ff[3] = fp8x2_to_float2((unsigned short)(q.y >> 16));
        #pragma unroll
        for (int p = 0; p < 4; p++) {
            float4 cA = sc[jb + 2*p];
            float4 cB = sc[jb + 2*p + 1];
            float kv = ff[p].x * cA.x; y += kv; wx += kv*cA.y; wy += kv*cA.z; wz += kv*cA.w;
            kv       = ff[p].y * cB.x; y += kv; wx += kv*cB.y; wy += kv*cB.z; wz += kv*cB.w;
        }
    }
    #pragma unroll
    for (int o = 16; o; o >>= 1) {
        y  += __shfl_xor_sync(~0u, y,  o);
        wx += __shfl_xor_sync(~0u, wx, o);
        wy += __shfl_xor_sync(~0u, wy, o);
        wz += __shfl_xor_sync(~0u, wz, o);
    }
    if (lane == 0) {
        float u    = g_u[b * MM + row];
        float sm   = u * y;                                  // pi row sum
        float surv = fminf(fmaxf(sm * (float)MM, 0.0f), 1.0f);
        float inv  = u / (sm + 1e-8f);
        const float* s  = x0    + ((size_t)b * MM + row) * 3;
        const float* vp = vpred + ((size_t)b * MM + row) * 3;
        float dx = (vp[0] - (wx * inv - s[0])) * surv;
        float dy = (vp[1] - (wy * inv - s[1])) * surv;
        float dz = (vp[2] - (wz * inv - s[2])) * surv;
        float ssq = dx*dx + dy*dy + dz*dz;
        float xv  = alpha[b * MM + row];
        float bce = fmaxf(xv, 0.0f) - xv * surv + log1pf(__expf(-fabsf(xv)));
        red[w][0] = ssq; red[w][1] = surv; red[w][2] = bce;
    }
    __syncthreads();
    if (threadIdx.x == 0) {
        float a0 = 0, a1 = 0, a2 = 0;
        #pragma unroll
        for (int i = 0; i < 8; i++) { a0 += red[i][0]; a1 += red[i][1]; a2 += red[i][2]; }
        atomicAdd(&g_acc[0], a0);
        atomicAdd(&g_acc[1], a1);
        atomicAdd(&g_acc[2], a2);
    }
}

__global__ void k_out(float* out) {
    out[0] = g_acc[0] / fmaxf(g_acc[1], 1.0f) + g_acc[2] * (1.0f / (float)(BB * MM));
}

// ---------------- launch -----------------------------------------------------
extern "C" void kernel_launch(void* const* d_in, const int* in_sizes, int n_in,
                              void* d_out, int out_size) {
    const float* x0  = (const float*)d_in[0];   // [B,M,3]
    const float* xgt = (const float*)d_in[1];   // [B,K,3]
    const float* vp  = (const float*)d_in[2];   // [B,M,3]
    const float* al  = (const float*)d_in[3];   // [B,M,1]
    // d_in[4] = t : unused by the reference loss
    (void)in_sizes; (void)n_in; (void)out_size;

    k_init<<<(BB * KK + 255) / 256, 256>>>();
    k_max<<<BB * MM / 8, 256>>>(x0, xgt);
    dim3 gb(KK / 64, MM / 64, BB);
    k_build<<<gb, 256>>>(x0, xgt);
    for (int it = 0; it < NITER; it++) {
        k_fused<<<BB * BLKS_PER_B, 256>>>();
        k_vfix<<<BB * 8, 256>>>();
    }
    k_final<<<BB * MM / 8, 256>>>(x0, xgt, vp, al);
    k_out<<<1, 1>>>((float*)d_out);
}

// round 15
// speedup vs baseline: 2.0162x; 1.4243x over previous
#include <cuda_runtime.h>
#include <cuda_fp16.h>

// Problem constants (fixed by setup_inputs)
#define BB 8
#define MM 4096
#define KK 2048
#define NITER 12
#define FI (5.0f/6.0f)     // reg_m / (reg_m + reg) = 0.5/0.6
#define REG 0.1f

// fused-kernel geometry: 256 thr (8 warps), 128 rows per block (16 batches
// of 8), warp owns a 256-column strip, lane owns 8 contiguous columns.
#define ROWS_PER_BLK 128
#define NBATCH       (ROWS_PER_BLK/8)       // 16
#define BLKS_PER_B   (MM/ROWS_PER_BLK)      // 32 blocks per batch
#define NPART        BLKS_PER_B             // 32 column partials per batch

// ---------------- scratch (device globals; no runtime allocation) ----------
__device__ unsigned char g_K8[(size_t)BB*MM*KK];   // e4m3 K, [b][m][k]
__device__ float  g_ctp[(size_t)BB*NPART*KK];      // per-block column partials
__device__ float  g_u [BB*MM];
__device__ float  g_v [BB*KK];
__device__ float  g_max[BB];
__device__ float  g_acc[3];                        // ssq, sum_survival, sum_bce

// ---------------- fp8 helpers ------------------------------------------------
__device__ __forceinline__ float2 fp8x2_to_float2(unsigned short s) {
    unsigned int h;
    asm("cvt.rn.f16x2.e4m3x2 %0, %1;" : "=r"(h) : "h"(s));
    return __half22float2(*(__half2*)&h);
}
__device__ __forceinline__ __half2 fp8x2_to_half2(unsigned int s) {
    unsigned int h;
    asm("cvt.rn.f16x2.e4m3x2 %0, %1;" : "=r"(h) : "h"((unsigned short)s));
    return *(__half2*)&h;
}
__device__ __forceinline__ unsigned short float2_to_fp8x2(float lo, float hi) {
    unsigned short s;
    asm("cvt.rn.satfinite.e4m3x2.f32 %0, %1, %2;" : "=h"(s) : "f"(hi), "f"(lo));
    return s;  // first source -> high byte, second -> low byte
}

// ---------------- fast exp(-x) on the FMA pipe (x >= 0, x <= ~15) -----------
__device__ __forceinline__ float fast_exp_neg(float x) {
    float t  = -x * 1.4426950408889634f;          // log2(e)
    float fl = floorf(t);
    float f  = t - fl;                            // [0,1)
    float g  = f * 0.6931471805599453f;           // ln2 * f
    float p = 1.0f + g*(1.0f + g*(0.5f + g*(0.16666667f +
              g*(0.041666667f + g*(0.0083333333f + g*0.0013888889f)))));
    int i = (int)fl;
    return p * __int_as_float((i + 127) << 23);
}

// ---------------- init ------------------------------------------------------
__global__ void k_init() {
    int i = blockIdx.x * blockDim.x + threadIdx.x;
    if (i < BB * KK) g_v[i] = 1.0f / (float)KK;
    if (i < BB)      g_max[i] = 0.0f;
    if (i < 3)       g_acc[i] = 0.0f;
}

// ---------------- per-batch max of cost matrix ------------------------------
__global__ void __launch_bounds__(256) k_max(const float* __restrict__ x0,
                                             const float* __restrict__ xgt) {
    __shared__ float4 st[KK];
    __shared__ float  wm[8];
    int b    = blockIdx.x / (MM / 8);
    int row0 = (blockIdx.x % (MM / 8)) * 8;
    const float* tg = xgt + (size_t)b * KK * 3;
    for (int j = threadIdx.x; j < KK; j += 256) {
        float tx = tg[j*3], ty = tg[j*3+1], tz = tg[j*3+2];
        st[j] = make_float4(tx, ty, tz, tx*tx + ty*ty + tz*tz);
    }
    __syncthreads();
    int w = threadIdx.x >> 5, lane = threadIdx.x & 31;
    int row = row0 + w;
    const float* s = x0 + ((size_t)b * MM + row) * 3;
    float sx = s[0], sy = s[1], sz = s[2];
    float s2 = sx*sx + sy*sy + sz*sz;
    float mx = 0.0f;
    for (int j = lane; j < KK; j += 32) {
        float4 t = st[j];
        float c = s2 + t.w - 2.0f * (sx*t.x + sy*t.y + sz*t.z);
        mx = fmaxf(mx, c);
    }
    #pragma unroll
    for (int o = 16; o; o >>= 1) mx = fmaxf(mx, __shfl_xor_sync(~0u, mx, o));
    if (lane == 0) wm[w] = mx;
    __syncthreads();
    if (threadIdx.x == 0) {
        float m = wm[0];
        #pragma unroll
        for (int i = 1; i < 8; i++) m = fmaxf(m, wm[i]);
        atomicMax((int*)&g_max[b], __float_as_int(m));  // nonneg floats: int order ok
    }
}

// ---------------- build K (e4m3), FMA-pipe exp ------------------------------
__global__ void __launch_bounds__(256) k_build(const float* __restrict__ x0,
                                               const float* __restrict__ xgt) {
    __shared__ float4 ss[64], st[64];
    int b  = blockIdx.z;
    int r0 = blockIdx.y * 64, c0 = blockIdx.x * 64;
    if (threadIdx.x < 64) {
        int r = r0 + threadIdx.x;
        const float* s = x0 + ((size_t)b * MM + r) * 3;
        float x = s[0], y = s[1], z = s[2];
        ss[threadIdx.x] = make_float4(x, y, z, x*x + y*y + z*z);
    } else if (threadIdx.x < 128) {
        int c = c0 + threadIdx.x - 64;
        const float* t = xgt + ((size_t)b * KK + c) * 3;
        float x = t[0], y = t[1], z = t[2];
        st[threadIdx.x - 64] = make_float4(x, y, z, x*x + y*y + z*z);
    }
    __syncthreads();
    float scale = 1.0f / (REG * (g_max[b] + 1e-8f));
    #pragma unroll
    for (int e = 0; e < 8; e++) {
        int idx = threadIdx.x + 256 * e;          // 0..2047
        int r = idx >> 5, cp = idx & 31;          // row, column-pair
        float4 S = ss[r];
        float4 T0 = st[cp*2], T1 = st[cp*2+1];
        float c0v = fmaxf(S.w + T0.w - 2.0f*(S.x*T0.x + S.y*T0.y + S.z*T0.z), 0.0f);
        float c1v = fmaxf(S.w + T1.w - 2.0f*(S.x*T1.x + S.y*T1.y + S.z*T1.z), 0.0f);
        unsigned short pk = float2_to_fp8x2(fast_exp_neg(c0v*scale),
                                            fast_exp_neg(c1v*scale));
        *(unsigned short*)(g_K8 + ((size_t)b * MM + r0 + r) * KK + c0 + cp*2) = pk;
    }
}

// ---------------- fused Sinkhorn iteration (fp8 + half2, decode-once) --------
// Block: 128 rows x 2048 cols, 16 batches of 8 rows. Warp w owns cols
// [w*256,(w+1)*256); lane owns 8 (one uint2 of fp8 per row). Double-buffered
// loads; fp8 decoded ONCE per batch into half2 regs, reused in both phases.
__global__ void __launch_bounds__(256, 2) k_fused() {
    __shared__ float sv[KK];
    __shared__ float sdot[8][8][8];          // [batch&7][row-in-batch][warp]
    int b   = blockIdx.x >> 5;
    int blk = blockIdx.x & 31;
    for (int j = threadIdx.x; j < KK; j += 256) sv[j] = g_v[b * KK + j];
    __syncthreads();
    int w = threadIdx.x >> 5, lane = threadIdx.x & 31;
    int col0 = w * 256 + lane * 8;
    float4 va = *(const float4*)(sv + col0);
    float4 vb = *(const float4*)(sv + col0 + 4);
    __half2 vh0 = __floats2half2_rn(va.x*16.0f, va.y*16.0f);
    __half2 vh1 = __floats2half2_rn(va.z*16.0f, va.w*16.0f);
    __half2 vh2 = __floats2half2_rn(vb.x*16.0f, vb.y*16.0f);
    __half2 vh3 = __floats2half2_rn(vb.z*16.0f, vb.w*16.0f);
    const __half2 hz = __floats2half2_rn(0.0f, 0.0f);

    float ct[8];
    #pragma unroll
    for (int i = 0; i < 8; i++) ct[i] = 0.0f;
    __half2 cth0 = hz, cth1 = hz, cth2 = hz, cth3 = hz;

    const unsigned char* Kbase =
        g_K8 + ((size_t)b * MM + blk * ROWS_PER_BLK) * KK + col0;

    uint2 qA[8], qB[8];
    #pragma unroll
    for (int r = 0; r < 8; r++)
        qA[r] = *(const uint2*)(Kbase + (size_t)r * KK);

    #pragma unroll 1
    for (int batch = 0; batch < NBATCH; batch++) {
        if (batch < NBATCH - 1) {
            const unsigned char* nb = Kbase + (size_t)(batch + 1) * 8 * KK;
            #pragma unroll
            for (int r = 0; r < 8; r++)
                qB[r] = *(const uint2*)(nb + (size_t)r * KK);
        }

        // decode once per batch; reuse in dot and accumulate phases
        __half2 f[8][4];
        #pragma unroll
        for (int r = 0; r < 8; r++) {
            f[r][0] = fp8x2_to_half2(qA[r].x);
            f[r][1] = fp8x2_to_half2(qA[r].x >> 16);
            f[r][2] = fp8x2_to_half2(qA[r].y);
            f[r][3] = fp8x2_to_half2(qA[r].y >> 16);
        }

        int slot = batch & 7;
        #pragma unroll
        for (int r = 0; r < 8; r++) {
            __half2 p = __hmul2(f[r][0], vh0);
            p = __hfma2(f[r][1], vh1, p);
            p = __hfma2(f[r][2], vh2, p);
            p = __hfma2(f[r][3], vh3, p);
            float2 pf = __half22float2(p);
            float d = pf.x + pf.y;                 // carries x16 from vh
            #pragma unroll
            for (int o = 16; o; o >>= 1) d += __shfl_xor_sync(~0u, d, o);
            if (lane == r) sdot[slot][r][w] = d;
        }
        __syncthreads();

        float u_l = 0.0f;
        if (lane < 8) {
            float s = 0.0f;
            #pragma unroll
            for (int j = 0; j < 8; j++) s += sdot[slot][lane][j];
            // (a/y)^fi with a=1/M;  s = 16*y  =>  y*M = s*M/16
            u_l = exp2f(-FI * __log2f(s * ((float)MM * 0.0625f)));
            if (w == 0) g_u[b * MM + blk * ROWS_PER_BLK + batch * 8 + lane] = u_l;
        }
        #pragma unroll
        for (int r = 0; r < 8; r++) {
            float u = __shfl_sync(~0u, u_l, r);
            __half2 uh = __float2half2_rn(u * 16.0f);
            cth0 = __hfma2(f[r][0], uh, cth0);
            cth1 = __hfma2(f[r][1], uh, cth1);
            cth2 = __hfma2(f[r][2], uh, cth2);
            cth3 = __hfma2(f[r][3], uh, cth3);
            if (r == 3 || r == 7) {               // flush half partials -> fp32
                float2 c;
                c = __half22float2(cth0); ct[0] += c.x*0.0625f; ct[1] += c.y*0.0625f;
                c = __half22float2(cth1); ct[2] += c.x*0.0625f; ct[3] += c.y*0.0625f;
                c = __half22float2(cth2); ct[4] += c.x*0.0625f; ct[5] += c.y*0.0625f;
                c = __half22float2(cth3); ct[6] += c.x*0.0625f; ct[7] += c.y*0.0625f;
                cth0 = hz; cth1 = hz; cth2 = hz; cth3 = hz;
            }
        }
        #pragma unroll
        for (int r = 0; r < 8; r++) qA[r] = qB[r];
        // slot reuse (batch&7) is safe: >=7 barriers between a slot's reads
        // and its next write
    }

    float* dst = g_ctp + ((size_t)(b * NPART + blk)) * KK + col0;
    *(float4*)dst       = make_float4(ct[0], ct[1], ct[2], ct[3]);
    *(float4*)(dst + 4) = make_float4(ct[4], ct[5], ct[6], ct[7]);
}

// ---------------- finish v-update: reduce partials, v = (b/ct)^fi -----------
__global__ void __launch_bounds__(256) k_vfix() {
    int b  = blockIdx.x >> 3;               // 8 column-chunks per batch
    int c  = (blockIdx.x & 7) * 256 + threadIdx.x;
    const float* base = g_ctp + (size_t)b * NPART * KK + c;
    float acc = 0.0f;
    #pragma unroll
    for (int p = 0; p < NPART; p++) acc += base[(size_t)p * KK];
    g_v[b * KK + c] = exp2f(-FI * __log2f(acc * (float)KK));  // (b/ct)^fi
}

// ---------------- final: pi-derived quantities + loss partials ---------------
__global__ void __launch_bounds__(256) k_final(const float* __restrict__ x0,
                                               const float* __restrict__ xgt,
                                               const float* __restrict__ vpred,
                                               const float* __restrict__ alpha) {
    __shared__ float4 sc[KK];          // {v_j, t_x, t_y, t_z}
    __shared__ float  red[8][3];
    int b   = blockIdx.x / (MM / 8);
    int row = (blockIdx.x % (MM / 8)) * 8 + (threadIdx.x >> 5);
    const float* tg = xgt + (size_t)b * KK * 3;
    for (int j = threadIdx.x; j < KK; j += 256)
        sc[j] = make_float4(g_v[b * KK + j], tg[j*3], tg[j*3+1], tg[j*3+2]);
    __syncthreads();
    int w = threadIdx.x >> 5, lane = threadIdx.x & 31;
    const unsigned char* Kr = g_K8 + ((size_t)b * MM + row) * KK;
    float y = 0.0f, wx = 0.0f, wy = 0.0f, wz = 0.0f;
    #pragma unroll
    for (int k = 0; k < 8; k++) {
        uint2 q = *(const uint2*)(Kr + (size_t)(k * 32 + lane) * 8);
        int jb = (k * 32 + lane) * 8;
        float2 ff[4];
        ff[0] = fp8x2_to_float2((unsigned short)(q.x & 0xFFFF));
        ff[1] = fp8x2_to_float2((unsigned short)(q.x >> 16));
        ff[2] = fp8x2_to_float2((unsigned short)(q.y & 0xFFFF));
        ff[3] = fp8x2_to_float2((unsigned short)(q.y >> 16));
        #pragma unroll
        for (int p = 0; p < 4; p++) {
            float4 cA = sc[jb + 2*p];
            float4 cB = sc[jb + 2*p + 1];
            float kv = ff[p].x * cA.x; y += kv; wx += kv*cA.y; wy += kv*cA.z; wz += kv*cA.w;
            kv       = ff[p].y * cB.x; y += kv; wx += kv*cB.y; wy += kv*cB.z; wz += kv*cB.w;
        }
    }
    #pragma unroll
    for (int o = 16; o; o >>= 1) {
        y  += __shfl_xor_sync(~0u, y,  o);
        wx += __shfl_xor_sync(~0u, wx, o);
        wy += __shfl_xor_sync(~0u, wy, o);
        wz += __shfl_xor_sync(~0u, wz, o);
    }
    if (lane == 0) {
        float u    = g_u[b * MM + row];
        float sm   = u * y;                                  // pi row sum
        float surv = fminf(fmaxf(sm * (float)MM, 0.0f), 1.0f);
        float inv  = u / (sm + 1e-8f);
        const float* s  = x0    + ((size_t)b * MM + row) * 3;
        const float* vp = vpred + ((size_t)b * MM + row) * 3;
        float dx = (vp[0] - (wx * inv - s[0])) * surv;
        float dy = (vp[1] - (wy * inv - s[1])) * surv;
        float dz = (vp[2] - (wz * inv - s[2])) * surv;
        float ssq = dx*dx + dy*dy + dz*dz;
        float xv  = alpha[b * MM + row];
        float bce = fmaxf(xv, 0.0f) - xv * surv + log1pf(__expf(-fabsf(xv)));
        red[w][0] = ssq; red[w][1] = surv; red[w][2] = bce;
    }
    __syncthreads();
    if (threadIdx.x == 0) {
        float a0 = 0, a1 = 0, a2 = 0;
        #pragma unroll
        for (int i = 0; i < 8; i++) { a0 += red[i][0]; a1 += red[i][1]; a2 += red[i][2]; }
        atomicAdd(&g_acc[0], a0);
        atomicAdd(&g_acc[1], a1);
        atomicAdd(&g_acc[2], a2);
    }
}

__global__ void k_out(float* out) {
    out[0] = g_acc[0] / fmaxf(g_acc[1], 1.0f) + g_acc[2] * (1.0f / (float)(BB * MM));
}

// ---------------- launch -----------------------------------------------------
extern "C" void kernel_launch(void* const* d_in, const int* in_sizes, int n_in,
                              void* d_out, int out_size) {
    const float* x0  = (const float*)d_in[0];   // [B,M,3]
    const float* xgt = (const float*)d_in[1];   // [B,K,3]
    const float* vp  = (const float*)d_in[2];   // [B,M,3]
    const float* al  = (const float*)d_in[3];   // [B,M,1]
    // d_in[4] = t : unused by the reference loss
    (void)in_sizes; (void)n_in; (void)out_size;

    k_init<<<(BB * KK + 255) / 256, 256>>>();
    k_max<<<BB * MM / 8, 256>>>(x0, xgt);
    dim3 gb(KK / 64, MM / 64, BB);
    k_build<<<gb, 256>>>(x0, xgt);
    for (int it = 0; it < NITER; it++) {
        k_fused<<<BB * BLKS_PER_B, 256>>>();
        k_vfix<<<BB * 8, 256>>>();
    }
    k_final<<<BB * MM / 8, 256>>>(x0, xgt, vp, al);
    k_out<<<1, 1>>>((float*)d_out);
}

// round 17
// speedup vs baseline: 2.3343x; 1.1578x over previous
#include <cuda_runtime.h>
#include <cuda_fp16.h>

// Problem constants (fixed by setup_inputs)
#define BB 8
#define MM 4096
#define KK 2048
#define NITER 8
#define FI (5.0f/6.0f)     // reg_m / (reg_m + reg) = 0.5/0.6
#define REG 0.1f

// fused-kernel geometry: 256 thr (8 warps), 128 rows per block (16 batches
// of 8), warp owns a 256-column strip, lane owns 8 contiguous columns.
#define ROWS_PER_BLK 128
#define NBATCH       (ROWS_PER_BLK/8)       // 16
#define BLKS_PER_B   (MM/ROWS_PER_BLK)      // 32 blocks per batch
#define NPART        BLKS_PER_B             // 32 column partials per batch

// ---------------- scratch (device globals; no runtime allocation) ----------
__device__ unsigned char g_K8[(size_t)BB*MM*KK];   // e4m3 K, [b][m][k]
__device__ float  g_ctp[(size_t)BB*NPART*KK];      // per-block column partials
__device__ float  g_u [BB*MM];
__device__ float  g_v [BB*KK];
__device__ float  g_max[BB];
__device__ float  g_acc[3];                        // ssq, sum_survival, sum_bce

// ---------------- fp8 helpers ------------------------------------------------
__device__ __forceinline__ float2 fp8x2_to_float2(unsigned short s) {
    unsigned int h;
    asm("cvt.rn.f16x2.e4m3x2 %0, %1;" : "=r"(h) : "h"(s));
    return __half22float2(*(__half2*)&h);
}
__device__ __forceinline__ __half2 fp8x2_to_half2(unsigned int s) {
    unsigned int h;
    asm("cvt.rn.f16x2.e4m3x2 %0, %1;" : "=r"(h) : "h"((unsigned short)s));
    return *(__half2*)&h;
}
__device__ __forceinline__ unsigned short float2_to_fp8x2(float lo, float hi) {
    unsigned short s;
    asm("cvt.rn.satfinite.e4m3x2.f32 %0, %1, %2;" : "=h"(s) : "f"(hi), "f"(lo));
    return s;  // first source -> high byte, second -> low byte
}

// ---------------- fast exp(-x) on the FMA pipe (x >= 0, x <= ~15) -----------
__device__ __forceinline__ float fast_exp_neg(float x) {
    float t  = -x * 1.4426950408889634f;          // log2(e)
    float fl = floorf(t);
    float f  = t - fl;                            // [0,1)
    float g  = f * 0.6931471805599453f;           // ln2 * f
    float p = 1.0f + g*(1.0f + g*(0.5f + g*(0.16666667f +
              g*(0.041666667f + g*(0.0083333333f + g*0.0013888889f)))));
    int i = (int)fl;
    return p * __int_as_float((i + 127) << 23);
}

// ---------------- init ------------------------------------------------------
__global__ void k_init() {
    int i = blockIdx.x * blockDim.x + threadIdx.x;
    if (i < BB * KK) g_v[i] = 1.0f / (float)KK;
    if (i < BB)      g_max[i] = 0.0f;
    if (i < 3)       g_acc[i] = 0.0f;
}

// ---------------- per-batch max of cost matrix ------------------------------
__global__ void __launch_bounds__(256) k_max(const float* __restrict__ x0,
                                             const float* __restrict__ xgt) {
    __shared__ float4 st[KK];
    __shared__ float  wm[8];
    int b    = blockIdx.x / (MM / 8);
    int row0 = (blockIdx.x % (MM / 8)) * 8;
    const float* tg = xgt + (size_t)b * KK * 3;
    for (int j = threadIdx.x; j < KK; j += 256) {
        float tx = tg[j*3], ty = tg[j*3+1], tz = tg[j*3+2];
        st[j] = make_float4(tx, ty, tz, tx*tx + ty*ty + tz*tz);
    }
    __syncthreads();
    int w = threadIdx.x >> 5, lane = threadIdx.x & 31;
    int row = row0 + w;
    const float* s = x0 + ((size_t)b * MM + row) * 3;
    float sx = s[0], sy = s[1], sz = s[2];
    float s2 = sx*sx + sy*sy + sz*sz;
    float mx = 0.0f;
    for (int j = lane; j < KK; j += 32) {
        float4 t = st[j];
        float c = s2 + t.w - 2.0f * (sx*t.x + sy*t.y + sz*t.z);
        mx = fmaxf(mx, c);
    }
    #pragma unroll
    for (int o = 16; o; o >>= 1) mx = fmaxf(mx, __shfl_xor_sync(~0u, mx, o));
    if (lane == 0) wm[w] = mx;
    __syncthreads();
    if (threadIdx.x == 0) {
        float m = wm[0];
        #pragma unroll
        for (int i = 1; i < 8; i++) m = fmaxf(m, wm[i]);
        atomicMax((int*)&g_max[b], __float_as_int(m));  // nonneg floats: int order ok
    }
}

// ---------------- build K (e4m3), FMA-pipe exp ------------------------------
__global__ void __launch_bounds__(256) k_build(const float* __restrict__ x0,
                                               const float* __restrict__ xgt) {
    __shared__ float4 ss[64], st[64];
    int b  = blockIdx.z;
    int r0 = blockIdx.y * 64, c0 = blockIdx.x * 64;
    if (threadIdx.x < 64) {
        int r = r0 + threadIdx.x;
        const float* s = x0 + ((size_t)b * MM + r) * 3;
        float x = s[0], y = s[1], z = s[2];
        ss[threadIdx.x] = make_float4(x, y, z, x*x + y*y + z*z);
    } else if (threadIdx.x < 128) {
        int c = c0 + threadIdx.x - 64;
        const float* t = xgt + ((size_t)b * KK + c) * 3;
        float x = t[0], y = t[1], z = t[2];
        st[threadIdx.x - 64] = make_float4(x, y, z, x*x + y*y + z*z);
    }
    __syncthreads();
    float scale = 1.0f / (REG * (g_max[b] + 1e-8f));
    #pragma unroll
    for (int e = 0; e < 8; e++) {
        int idx = threadIdx.x + 256 * e;          // 0..2047
        int r = idx >> 5, cp = idx & 31;          // row, column-pair
        float4 S = ss[r];
        float4 T0 = st[cp*2], T1 = st[cp*2+1];
        float c0v = fmaxf(S.w + T0.w - 2.0f*(S.x*T0.x + S.y*T0.y + S.z*T0.z), 0.0f);
        float c1v = fmaxf(S.w + T1.w - 2.0f*(S.x*T1.x + S.y*T1.y + S.z*T1.z), 0.0f);
        unsigned short pk = float2_to_fp8x2(fast_exp_neg(c0v*scale),
                                            fast_exp_neg(c1v*scale));
        *(unsigned short*)(g_K8 + ((size_t)b * MM + r0 + r) * KK + c0 + cp*2) = pk;
    }
}

// ---------------- fused Sinkhorn iteration (fp8 + half2, decode-once) --------
// Block: 128 rows x 2048 cols, 16 batches of 8 rows. Warp w owns cols
// [w*256,(w+1)*256); lane owns 8 (one uint2 of fp8 per row). Double-buffered
// loads; fp8 decoded ONCE per batch into half2 regs, reused in both phases.
__global__ void __launch_bounds__(256, 2) k_fused() {
    __shared__ float sv[KK];
    __shared__ float sdot[8][8][8];          // [batch&7][row-in-batch][warp]
    int b   = blockIdx.x >> 5;
    int blk = blockIdx.x & 31;
    for (int j = threadIdx.x; j < KK; j += 256) sv[j] = g_v[b * KK + j];
    __syncthreads();
    int w = threadIdx.x >> 5, lane = threadIdx.x & 31;
    int col0 = w * 256 + lane * 8;
    float4 va = *(const float4*)(sv + col0);
    float4 vb = *(const float4*)(sv + col0 + 4);
    __half2 vh0 = __floats2half2_rn(va.x*16.0f, va.y*16.0f);
    __half2 vh1 = __floats2half2_rn(va.z*16.0f, va.w*16.0f);
    __half2 vh2 = __floats2half2_rn(vb.x*16.0f, vb.y*16.0f);
    __half2 vh3 = __floats2half2_rn(vb.z*16.0f, vb.w*16.0f);
    const __half2 hz = __floats2half2_rn(0.0f, 0.0f);

    float ct[8];
    #pragma unroll
    for (int i = 0; i < 8; i++) ct[i] = 0.0f;
    __half2 cth0 = hz, cth1 = hz, cth2 = hz, cth3 = hz;

    const unsigned char* Kbase =
        g_K8 + ((size_t)b * MM + blk * ROWS_PER_BLK) * KK + col0;

    uint2 qA[8], qB[8];
    #pragma unroll
    for (int r = 0; r < 8; r++)
        qA[r] = *(const uint2*)(Kbase + (size_t)r * KK);

    #pragma unroll 1
    for (int batch = 0; batch < NBATCH; batch++) {
        if (batch < NBATCH - 1) {
            const unsigned char* nb = Kbase + (size_t)(batch + 1) * 8 * KK;
            #pragma unroll
            for (int r = 0; r < 8; r++)
                qB[r] = *(const uint2*)(nb + (size_t)r * KK);
        }

        // decode once per batch; reuse in dot and accumulate phases
        __half2 f[8][4];
        #pragma unroll
        for (int r = 0; r < 8; r++) {
            f[r][0] = fp8x2_to_half2(qA[r].x);
            f[r][1] = fp8x2_to_half2(qA[r].x >> 16);
            f[r][2] = fp8x2_to_half2(qA[r].y);
            f[r][3] = fp8x2_to_half2(qA[r].y >> 16);
        }

        int slot = batch & 7;
        #pragma unroll
        for (int r = 0; r < 8; r++) {
            __half2 p = __hmul2(f[r][0], vh0);
            p = __hfma2(f[r][1], vh1, p);
            p = __hfma2(f[r][2], vh2, p);
            p = __hfma2(f[r][3], vh3, p);
            float2 pf = __half22float2(p);
            float d = pf.x + pf.y;                 // carries x16 from vh
            #pragma unroll
            for (int o = 16; o; o >>= 1) d += __shfl_xor_sync(~0u, d, o);
            if (lane == r) sdot[slot][r][w] = d;
        }
        __syncthreads();

        float u_l = 0.0f;
        if (lane < 8) {
            float s = 0.0f;
            #pragma unroll
            for (int j = 0; j < 8; j++) s += sdot[slot][lane][j];
            // (a/y)^fi with a=1/M;  s = 16*y  =>  y*M = s*M/16
            u_l = exp2f(-FI * __log2f(s * ((float)MM * 0.0625f)));
            if (w == 0) g_u[b * MM + blk * ROWS_PER_BLK + batch * 8 + lane] = u_l;
        }
        #pragma unroll
        for (int r = 0; r < 8; r++) {
            float u = __shfl_sync(~0u, u_l, r);
            __half2 uh = __float2half2_rn(u * 16.0f);
            cth0 = __hfma2(f[r][0], uh, cth0);
            cth1 = __hfma2(f[r][1], uh, cth1);
            cth2 = __hfma2(f[r][2], uh, cth2);
            cth3 = __hfma2(f[r][3], uh, cth3);
            if (r == 3 || r == 7) {               // flush half partials -> fp32
                float2 c;
                c = __half22float2(cth0); ct[0] += c.x*0.0625f; ct[1] += c.y*0.0625f;
                c = __half22float2(cth1); ct[2] += c.x*0.0625f; ct[3] += c.y*0.0625f;
                c = __half22float2(cth2); ct[4] += c.x*0.0625f; ct[5] += c.y*0.0625f;
                c = __half22float2(cth3); ct[6] += c.x*0.0625f; ct[7] += c.y*0.0625f;
                cth0 = hz; cth1 = hz; cth2 = hz; cth3 = hz;
            }
        }
        #pragma unroll
        for (int r = 0; r < 8; r++) qA[r] = qB[r];
        // slot reuse (batch&7) is safe: >=7 barriers between a slot's reads
        // and its next write
    }

    float* dst = g_ctp + ((size_t)(b * NPART + blk)) * KK + col0;
    *(float4*)dst       = make_float4(ct[0], ct[1], ct[2], ct[3]);
    *(float4*)(dst + 4) = make_float4(ct[4], ct[5], ct[6], ct[7]);
}

// ---------------- finish v-update: reduce partials, v = (b/ct)^fi -----------
__global__ void __launch_bounds__(256) k_vfix() {
    int b  = blockIdx.x >> 3;               // 8 column-chunks per batch
    int c  = (blockIdx.x & 7) * 256 + threadIdx.x;
    const float* base = g_ctp + (size_t)b * NPART * KK + c;
    float acc = 0.0f;
    #pragma unroll
    for (int p = 0; p < NPART; p++) acc += base[(size_t)p * KK];
    g_v[b * KK + c] = exp2f(-FI * __log2f(acc * (float)KK));  // (b/ct)^fi
}

// ---------------- final: pi-derived quantities + loss partials ---------------
__global__ void __launch_bounds__(256) k_final(const float* __restrict__ x0,
                                               const float* __restrict__ xgt,
                                               const float* __restrict__ vpred,
                                               const float* __restrict__ alpha) {
    __shared__ float4 sc[KK];          // {v_j, t_x, t_y, t_z}
    __shared__ float  red[8][3];
    int b   = blockIdx.x / (MM / 8);
    int row = (blockIdx.x % (MM / 8)) * 8 + (threadIdx.x >> 5);
    const float* tg = xgt + (size_t)b * KK * 3;
    for (int j = threadIdx.x; j < KK; j += 256)
        sc[j] = make_float4(g_v[b * KK + j], tg[j*3], tg[j*3+1], tg[j*3+2]);
    __syncthreads();
    int w = threadIdx.x >> 5, lane = threadIdx.x & 31;
    const unsigned char* Kr = g_K8 + ((size_t)b * MM + row) * KK;
    float y = 0.0f, wx = 0.0f, wy = 0.0f, wz = 0.0f;
    #pragma unroll
    for (int k = 0; k < 8; k++) {
        uint2 q = *(const uint2*)(Kr + (size_t)(k * 32 + lane) * 8);
        int jb = (k * 32 + lane) * 8;
        float2 ff[4];
        ff[0] = fp8x2_to_float2((unsigned short)(q.x & 0xFFFF));
        ff[1] = fp8x2_to_float2((unsigned short)(q.x >> 16));
        ff[2] = fp8x2_to_float2((unsigned short)(q.y & 0xFFFF));
        ff[3] = fp8x2_to_float2((unsigned short)(q.y >> 16));
        #pragma unroll
        for (int p = 0; p < 4; p++) {
            float4 cA = sc[jb + 2*p];
            float4 cB = sc[jb + 2*p + 1];
            float kv = ff[p].x * cA.x; y += kv; wx += kv*cA.y; wy += kv*cA.z; wz += kv*cA.w;
            kv       = ff[p].y * cB.x; y += kv; wx += kv*cB.y; wy += kv*cB.z; wz += kv*cB.w;
        }
    }
    #pragma unroll
    for (int o = 16; o; o >>= 1) {
        y  += __shfl_xor_sync(~0u, y,  o);
        wx += __shfl_xor_sync(~0u, wx, o);
        wy += __shfl_xor_sync(~0u, wy, o);
        wz += __shfl_xor_sync(~0u, wz, o);
    }
    if (lane == 0) {
        float u    = g_u[b * MM + row];
        float sm   = u * y;                                  // pi row sum
        float surv = fminf(fmaxf(sm * (float)MM, 0.0f), 1.0f);
        float inv  = u / (sm + 1e-8f);
        const float* s  = x0    + ((size_t)b * MM + row) * 3;
        const float* vp = vpred + ((size_t)b * MM + row) * 3;
        float dx = (vp[0] - (wx * inv - s[0])) * surv;
        float dy = (vp[1] - (wy * inv - s[1])) * surv;
        float dz = (vp[2] - (wz * inv - s[2])) * surv;
        float ssq = dx*dx + dy*dy + dz*dz;
        float xv  = alpha[b * MM + row];
        float bce = fmaxf(xv, 0.0f) - xv * surv + log1pf(__expf(-fabsf(xv)));
        red[w][0] = ssq; red[w][1] = surv; red[w][2] = bce;
    }
    __syncthreads();
    if (threadIdx.x == 0) {
        float a0 = 0, a1 = 0, a2 = 0;
        #pragma unroll
        for (int i = 0; i < 8; i++) { a0 += red[i][0]; a1 += red[i][1]; a2 += red[i][2]; }
        atomicAdd(&g_acc[0], a0);
        atomicAdd(&g_acc[1], a1);
        atomicAdd(&g_acc[2], a2);
    }
}

__global__ void k_out(float* out) {
    out[0] = g_acc[0] / fmaxf(g_acc[1], 1.0f) + g_acc[2] * (1.0f / (float)(BB * MM));
}

// ---------------- launch -----------------------------------------------------
extern "C" void kernel_launch(void* const* d_in, const int* in_sizes, int n_in,
                              void* d_out, int out_size) {
    const float* x0  = (const float*)d_in[0];   // [B,M,3]
    const float* xgt = (const float*)d_in[1];   // [B,K,3]
    const float* vp  = (const float*)d_in[2];   // [B,M,3]
    const float* al  = (const float*)d_in[3];   // [B,M,1]
    // d_in[4] = t : unused by the reference loss
    (void)in_sizes; (void)n_in; (void)out_size;

    k_init<<<(BB * KK + 255) / 256, 256>>>();
    k_max<<<BB * MM / 8, 256>>>(x0, xgt);
    dim3 gb(KK / 64, MM / 64, BB);
    k_build<<<gb, 256>>>(x0, xgt);
    for (int it = 0; it < NITER; it++) {
        k_fused<<<BB * BLKS_PER_B, 256>>>();
        k_vfix<<<BB * 8, 256>>>();
    }
    k_final<<<BB * MM / 8, 256>>>(x0, xgt, vp, al);
    k_out<<<1, 1>>>((float*)d_out);
}